// round 1
// baseline (speedup 1.0000x reference)
#include <cuda_runtime.h>
#include <cstddef>

#define N_NODES 50000
#define DIN 96
#define DOUT 256

// Scratch (allocation-free rule: __device__ globals)
__device__ float g_agg[(size_t)N_NODES * DIN];    // 19.2 MB
__device__ float g_h[(size_t)N_NODES * DOUT];     // 51.2 MB

// ---------------------------------------------------------------------------
// agg = eps * x   (GIN residual folded into the SpMM accumulator init)
// ---------------------------------------------------------------------------
__global__ void init_agg_kernel(const float* __restrict__ x,
                                const float* __restrict__ eps, int n4) {
    int i = blockIdx.x * blockDim.x + threadIdx.x;
    if (i < n4) {
        float e = eps[0];
        float4 v = ((const float4*)x)[i];
        v.x *= e; v.y *= e; v.z *= e; v.w *= e;
        ((float4*)g_agg)[i] = v;
    }
}

// ---------------------------------------------------------------------------
// agg[dst] += vals[e] * x[src]  via vectorized L2 reductions (red.v4.f32)
// One thread per (edge, 16B chunk): 24 chunks cover DIN=96 floats.
// ---------------------------------------------------------------------------
__global__ void spmm_kernel(const float* __restrict__ x,
                            const int* __restrict__ src,
                            const int* __restrict__ dst,
                            const float* __restrict__ vals, int total) {
    int idx = blockIdx.x * blockDim.x + threadIdx.x;
    if (idx >= total) return;
    int e = idx / 24;
    int c = idx - e * 24;
    int s = src[e];
    int d = dst[e];
    float v = vals[e];
    float4 xv = *(const float4*)(x + (size_t)s * DIN + c * 4);
    float* p = g_agg + (size_t)d * DIN + c * 4;
    asm volatile("red.global.add.v4.f32 [%0], {%1,%2,%3,%4};"
                 :: "l"(p), "f"(v * xv.x), "f"(v * xv.y),
                    "f"(v * xv.z), "f"(v * xv.w)
                 : "memory");
}

// ---------------------------------------------------------------------------
// Tiled SGEMM: C[M,256] = A[M,K] @ B[K,256], BM=BN=128, BK=32,
// 256 threads, 8x8 register microtile. Optional fused BN(inference)+ReLU.
// ---------------------------------------------------------------------------
template <bool FUSE_BN>
__global__ void __launch_bounds__(256)
gemm_kernel(const float* __restrict__ A, const float* __restrict__ B,
            float* __restrict__ C, int M, int K,
            const float* __restrict__ gamma, const float* __restrict__ beta,
            const float* __restrict__ mean, const float* __restrict__ var) {
    __shared__ float As[32][132];   // stride 132 floats: 16B-aligned, fewer STS conflicts
    __shared__ float Bs[32][128];

    const int tid = threadIdx.x;
    const int rowBlock = blockIdx.y * 128;
    const int colBlock = blockIdx.x * 128;

    float acc[8][8];
#pragma unroll
    for (int i = 0; i < 8; i++)
#pragma unroll
        for (int j = 0; j < 8; j++) acc[i][j] = 0.f;

    const int rg = (tid >> 4) * 8;
    const int cg = (tid & 15) * 8;

    for (int k0 = 0; k0 < K; k0 += 32) {
        // Load A tile [128 rows x 32 k], store transposed As[k][row]
#pragma unroll
        for (int i = 0; i < 4; i++) {
            int f = tid + i * 256;
            int r = f >> 3;
            int kq = f & 7;
            int grow = rowBlock + r;
            float4 v = make_float4(0.f, 0.f, 0.f, 0.f);
            if (grow < M)
                v = *(const float4*)(A + (size_t)grow * K + (k0 + kq * 4));
            As[kq * 4 + 0][r] = v.x;
            As[kq * 4 + 1][r] = v.y;
            As[kq * 4 + 2][r] = v.z;
            As[kq * 4 + 3][r] = v.w;
        }
        // Load B tile [32 k x 128 cols]
#pragma unroll
        for (int i = 0; i < 4; i++) {
            int f = tid + i * 256;
            int kr = f >> 5;
            int cq = f & 31;
            *(float4*)&Bs[kr][cq * 4] =
                *(const float4*)(B + (size_t)(k0 + kr) * DOUT + colBlock + cq * 4);
        }
        __syncthreads();

#pragma unroll 8
        for (int k = 0; k < 32; k++) {
            float a[8], b[8];
            *(float4*)(a)     = *(const float4*)&As[k][rg];
            *(float4*)(a + 4) = *(const float4*)&As[k][rg + 4];
            *(float4*)(b)     = *(const float4*)&Bs[k][cg];
            *(float4*)(b + 4) = *(const float4*)&Bs[k][cg + 4];
#pragma unroll
            for (int i = 0; i < 8; i++)
#pragma unroll
                for (int j = 0; j < 8; j++)
                    acc[i][j] = fmaf(a[i], b[j], acc[i][j]);
        }
        __syncthreads();
    }

    // Epilogue (optionally fused inference-BN + ReLU)
    float sc[8], bi[8];
    if (FUSE_BN) {
#pragma unroll
        for (int j = 0; j < 8; j++) {
            int col = colBlock + cg + j;
            float s = gamma[col] * rsqrtf(var[col] + 1e-3f);
            sc[j] = s;
            bi[j] = beta[col] - mean[col] * s;
        }
    }
#pragma unroll
    for (int i = 0; i < 8; i++) {
        int grow = rowBlock + rg + i;
        if (grow < M) {
            float out[8];
#pragma unroll
            for (int j = 0; j < 8; j++) {
                float v = acc[i][j];
                if (FUSE_BN) v = fmaxf(fmaf(v, sc[j], bi[j]), 0.f);
                out[j] = v;
            }
            float* cp = C + (size_t)grow * DOUT + colBlock + cg;
            *(float4*)cp       = *(float4*)out;
            *(float4*)(cp + 4) = *(float4*)(out + 4);
        }
    }
}

// ---------------------------------------------------------------------------
extern "C" void kernel_launch(void* const* d_in, const int* in_sizes, int n_in,
                              void* d_out, int out_size) {
    const float* x     = (const float*)d_in[0];
    const int*   src   = (const int*)d_in[1];
    const int*   dst   = (const int*)d_in[2];
    const float* vals  = (const float*)d_in[3];
    const float* eps   = (const float*)d_in[4];
    const float* W0    = (const float*)d_in[5];
    const float* W1    = (const float*)d_in[6];
    const float* gamma = (const float*)d_in[7];
    const float* beta  = (const float*)d_in[8];
    const float* mean  = (const float*)d_in[9];
    const float* var   = (const float*)d_in[10];

    int N = in_sizes[0] / DIN;
    int E = in_sizes[1];

    float *agg, *h;
    cudaGetSymbolAddress((void**)&agg, g_agg);
    cudaGetSymbolAddress((void**)&h, g_h);

    // 1. agg = eps * x
    int n4 = N * (DIN / 4);
    init_agg_kernel<<<(n4 + 255) / 256, 256>>>(x, eps, n4);

    // 2. scatter-add edge messages
    int total = E * (DIN / 4);
    spmm_kernel<<<(total + 255) / 256, 256>>>(x, src, dst, vals, total);

    // 3. h = relu(bn(agg @ W0))
    dim3 grid(DOUT / 128, (N + 127) / 128);
    gemm_kernel<true><<<grid, 256>>>(agg, W0, h, N, DIN, gamma, beta, mean, var);

    // 4. out = h @ W1
    gemm_kernel<false><<<grid, 256>>>(h, W1, (float*)d_out, N, DOUT,
                                      nullptr, nullptr, nullptr, nullptr);
}